// round 1
// baseline (speedup 1.0000x reference)
#include <cuda_runtime.h>
#include <cuda_fp16.h>
#include <mma.h>
#include <cstdint>

using namespace nvcuda;

// Problem dims
#define B_  16
#define L_  512
#define Kn_ 48
#define E_  128
#define D_  384
#define H_  128

#define TILE_M  96
#define NTILES  4096          // (B*L*K)/TILE_M = 393216/96

// ---- smem layout (bytes) for k_main ----
// A1s   [96][392] half : 0       .. 75264
// Xs    [96][136] half : 75264   .. 101376
// W1s   [128][392]half : 101376  .. 201728
// C1s   [96][388] f32  : alias @75264  (after GEMM1; Xs/W1s dead)  end 224256
// CHK0  [64][392] half : alias @76800  (after A1s written; C1s dead)
// CHK1  [64][392] half : alias @126976
// C2s   [96][388] f32  : alias @76800  (after GEMM2; chunks dead)  end 225792
// idxs  [96] int       : 225792 .. 226176
#define OFF_A1S   0
#define OFF_XS    75264
#define OFF_W1S   101376
#define OFF_C1S   75264
#define OFF_CHK0  76800
#define OFF_CHK1  126976
#define OFF_C2S   76800
#define OFF_IDX   225792
#define SMEM_MAIN 226304

// head kernel smem
#define HOFF_HS   0            // [64][388] f32 = 99328
#define HOFF_H1   99328        // [64][132] f32 = 33792
#define HOFF_H2   133120       // [64][65]  f32 = 16640
#define SMEM_HEAD 149760

// ---- device scratch (no allocations allowed) ----
__device__ __align__(16) __half g_W1h[E_ * D_];
__device__ __align__(16) __half g_W2h[D_ * D_];
__device__ __align__(16) float  g_hbuf[(size_t)B_ * L_ * D_];
__device__ __align__(16) float  g_dG[B_ * L_];

__device__ __forceinline__ float geluf(float x) {
    return 0.5f * x * (1.0f + erff(x * 0.7071067811865476f));
}

__device__ __forceinline__ void cp_async16(void* dst, const void* src) {
    unsigned s = (unsigned)__cvta_generic_to_shared(dst);
    asm volatile("cp.async.cg.shared.global [%0], [%1], 16;\n" :: "r"(s), "l"(src) : "memory");
}
__device__ __forceinline__ void cp_commit() { asm volatile("cp.async.commit_group;\n" ::: "memory"); }
__device__ __forceinline__ void cp_wait0()  { asm volatile("cp.async.wait_group 0;\n" ::: "memory"); }

// ============================================================
// weight fp32 -> fp16 conversion (tiny)
// ============================================================
__global__ void k_convert(const float* __restrict__ fw1, const float* __restrict__ fw2) {
    int stride = gridDim.x * blockDim.x;
    int i0 = blockIdx.x * blockDim.x + threadIdx.x;
    for (int q = i0; q < E_ * D_; q += stride) g_W1h[q] = __float2half_rn(fw1[q]);
    for (int q = i0; q < D_ * D_; q += stride) g_W2h[q] = __float2half_rn(fw2[q]);
}

// ============================================================
// fused: GEMM1 + gelu + GEMM2 + gelu + gather(x_j) + K-reduce
// one CTA = 96 rows = 2 complete (b,l) groups -> writes 2 rows of h
// ============================================================
__global__ void __launch_bounds__(256, 1)
k_main(const float* __restrict__ h_V, const float* __restrict__ h_E,
       const float* __restrict__ fb1, const float* __restrict__ fb2,
       const int* __restrict__ E_idx)
{
    extern __shared__ unsigned char smem[];
    __half* A1s  = (__half*)(smem + OFF_A1S);    // [96][392]
    __half* Xs   = (__half*)(smem + OFF_XS);     // [96][136]
    __half* W1s  = (__half*)(smem + OFF_W1S);    // [128][392]
    float*  C1s  = (float*)(smem + OFF_C1S);     // [96][388]
    float*  C2s  = (float*)(smem + OFF_C2S);     // [96][388]
    __half* chk0 = (__half*)(smem + OFF_CHK0);   // [64][392]
    __half* chk1 = (__half*)(smem + OFF_CHK1);   // [64][392]
    int*    idxs = (int*)(smem + OFF_IDX);

    const int t = threadIdx.x;
    const int tile = blockIdx.x;
    const int rowbase = tile * TILE_M;
    const int b = rowbase / (L_ * Kn_);          // whole tile within one batch

    if (t < TILE_M) idxs[t] = E_idx[rowbase + t];

    // ---- stage W1 (fp16, cp.async) and X tile (fp32->fp16) ----
    for (int q = t; q < (E_ * D_) / 8; q += 256) {        // 6144 x 16B
        int r = q / 48, c8 = q - r * 48;
        cp_async16(W1s + r * 392 + c8 * 8, g_W1h + r * 384 + c8 * 8);
    }
    cp_commit();
    {
        const float4* Xg = reinterpret_cast<const float4*>(h_E + (size_t)rowbase * E_);
        for (int q = t; q < (TILE_M * E_) / 4; q += 256) {  // 3072 float4
            int m = q >> 5, c4 = q & 31;
            float4 v = Xg[q];
            __half2* d = reinterpret_cast<__half2*>(Xs + m * 136 + c4 * 4);
            d[0] = __floats2half2_rn(v.x, v.y);
            d[1] = __floats2half2_rn(v.z, v.w);
        }
    }
    cp_wait0();
    __syncthreads();

    // warp tiling: 8 warps in 2(m) x 4(n); warp tile = 48 x 96
    const int warp  = t >> 5;
    const int wm    = warp >> 2;     // 0..1
    const int wn    = warp & 3;      // 0..3
    const int mrow0 = wm * 48;
    const int ncol0 = wn * 96;

    wmma::fragment<wmma::accumulator, 16, 16, 16, float> acc[3][6];
#pragma unroll
    for (int i = 0; i < 3; i++)
#pragma unroll
        for (int j = 0; j < 6; j++) wmma::fill_fragment(acc[i][j], 0.0f);

    // ---- GEMM1: [96,128] @ [128,384] ----
#pragma unroll
    for (int k = 0; k < E_; k += 16) {
        wmma::fragment<wmma::matrix_a, 16, 16, 16, __half, wmma::row_major> af[3];
#pragma unroll
        for (int i = 0; i < 3; i++)
            wmma::load_matrix_sync(af[i], Xs + (mrow0 + i * 16) * 136 + k, 136);
#pragma unroll
        for (int j = 0; j < 6; j++) {
            wmma::fragment<wmma::matrix_b, 16, 16, 16, __half, wmma::row_major> bf;
            wmma::load_matrix_sync(bf, W1s + k * 392 + ncol0 + j * 16, 392);
#pragma unroll
            for (int i = 0; i < 3; i++) wmma::mma_sync(acc[i][j], af[i], bf, acc[i][j]);
        }
    }
    __syncthreads();   // all mma reads of Xs/W1s done before aliasing with C1s
#pragma unroll
    for (int i = 0; i < 3; i++)
#pragma unroll
        for (int j = 0; j < 6; j++)
            wmma::store_matrix_sync(C1s + (mrow0 + i * 16) * 388 + ncol0 + j * 16,
                                    acc[i][j], 388, wmma::mem_row_major);
    __syncthreads();

    // ---- bias + gelu -> A1s (fp16) ----
    for (int e = t; e < TILE_M * D_; e += 256) {
        int m = e / D_, n = e - m * D_;
        float v = C1s[m * 388 + n] + fb1[n];
        A1s[m * 392 + n] = __float2half_rn(geluf(v));
    }
    __syncthreads();   // C1s dead; chunk buffers may overwrite

    // ---- GEMM2: [96,384] @ [384,384], W2 streamed in 6 chunks of k=64 ----
#pragma unroll
    for (int i = 0; i < 3; i++)
#pragma unroll
        for (int j = 0; j < 6; j++) wmma::fill_fragment(acc[i][j], 0.0f);

    auto load_chunk = [&](int c, __half* dst) {
        const __half* src = g_W2h + (size_t)c * 64 * D_;
        for (int q = t; q < 3072; q += 256) {         // 64 rows x 48 x 16B
            int r = q / 48, c8 = q - r * 48;
            cp_async16(dst + r * 392 + c8 * 8, src + r * 384 + c8 * 8);
        }
    };
    load_chunk(0, chk0);
    cp_commit(); cp_wait0();
    __syncthreads();

    for (int c = 0; c < 6; c++) {
        __half* cur = (c & 1) ? chk1 : chk0;
        if (c < 5) { load_chunk(c + 1, (c & 1) ? chk0 : chk1); cp_commit(); }
#pragma unroll
        for (int ks = 0; ks < 4; ks++) {
            int k2 = c * 64 + ks * 16;
            wmma::fragment<wmma::matrix_a, 16, 16, 16, __half, wmma::row_major> af[3];
#pragma unroll
            for (int i = 0; i < 3; i++)
                wmma::load_matrix_sync(af[i], A1s + (mrow0 + i * 16) * 392 + k2, 392);
#pragma unroll
            for (int j = 0; j < 6; j++) {
                wmma::fragment<wmma::matrix_b, 16, 16, 16, __half, wmma::row_major> bf;
                wmma::load_matrix_sync(bf, cur + (ks * 16) * 392 + ncol0 + j * 16, 392);
#pragma unroll
                for (int i = 0; i < 3; i++) wmma::mma_sync(acc[i][j], af[i], bf, acc[i][j]);
            }
        }
        if (c < 5) cp_wait0();
        __syncthreads();
    }

    // ---- store C2, then fused bias+gelu+gather+K-reduce epilogue ----
#pragma unroll
    for (int i = 0; i < 3; i++)
#pragma unroll
        for (int j = 0; j < 6; j++)
            wmma::store_matrix_sync(C2s + (mrow0 + i * 16) * 388 + ncol0 + j * 16,
                                    acc[i][j], 388, wmma::mem_row_major);
    __syncthreads();

    {
        const int n0 = t;                 // < 256
        const int n1 = 256 + t;           // valid when t < 128
        const bool has1 = (t < 128);
        float fa = fb2[n0];
        float fbv = has1 ? fb2[n1] : 0.0f;
        const float* hVb = h_V + (size_t)b * L_ * D_;

        float a00 = 0.f, a01 = 0.f, a10 = 0.f, a11 = 0.f;
#pragma unroll 4
        for (int m = 0; m < 48; m++) {
            const float* xr = hVb + (size_t)idxs[m] * D_;
            float w0 = geluf(C2s[m * 388 + n0] + fa);
            a00 += w0 * xr[n0];
            if (has1) { float w1 = geluf(C2s[m * 388 + n1] + fbv); a01 += w1 * xr[n1]; }
        }
#pragma unroll 4
        for (int m = 48; m < 96; m++) {
            const float* xr = hVb + (size_t)idxs[m] * D_;
            float w0 = geluf(C2s[m * 388 + n0] + fa);
            a10 += w0 * xr[n0];
            if (has1) { float w1 = geluf(C2s[m * 388 + n1] + fbv); a11 += w1 * xr[n1]; }
        }
        const size_t g0 = (size_t)tile * 2;
        g_hbuf[g0 * D_ + n0] = a00;
        g_hbuf[(g0 + 1) * D_ + n0] = a10;
        if (has1) {
            g_hbuf[g0 * D_ + n1] = a01;
            g_hbuf[(g0 + 1) * D_ + n1] = a11;
        }
    }
}

// ============================================================
// head MLP: h[8192,384] -> gelu(@hw1) -> gelu(@hw2) -> @hw3 -> dG[8192]
// one CTA = 64 rows, 256 threads
// ============================================================
__global__ void __launch_bounds__(256, 1)
k_head(const float* __restrict__ hw1, const float* __restrict__ hb1,
       const float* __restrict__ hw2, const float* __restrict__ hb2,
       const float* __restrict__ hw3, const float* __restrict__ hb3)
{
    extern __shared__ unsigned char sm[];
    float* hs  = (float*)(sm + HOFF_HS);   // [64][388]
    float* h1s = (float*)(sm + HOFF_H1);   // [64][132]
    float* h2s = (float*)(sm + HOFF_H2);   // [64][65]
    const int t = threadIdx.x;
    const int row0 = blockIdx.x * 64;

    for (int e = t; e < 64 * D_; e += 256) {
        int r = e / D_, n = e - r * D_;
        hs[r * 388 + n] = g_hbuf[(size_t)(row0 + r) * D_ + n];
    }
    __syncthreads();

    // hidden1: unit u = t%128, rows block rb = t/128 (32 rows each)
    {
        const int u = t & 127, rb = t >> 7;
        float accv[32];
#pragma unroll
        for (int r = 0; r < 32; r++) accv[r] = 0.f;
        const float* hb = hs + (rb * 32) * 388;
        for (int d0 = 0; d0 < D_; d0 += 4) {
            float w0 = hw1[(d0 + 0) * H_ + u];
            float w1 = hw1[(d0 + 1) * H_ + u];
            float w2 = hw1[(d0 + 2) * H_ + u];
            float w3 = hw1[(d0 + 3) * H_ + u];
#pragma unroll
            for (int r = 0; r < 32; r++) {
                float4 hv = *reinterpret_cast<const float4*>(hb + r * 388 + d0);
                accv[r] += hv.x * w0 + hv.y * w1 + hv.z * w2 + hv.w * w3;
            }
        }
        float b1 = hb1[u];
#pragma unroll
        for (int r = 0; r < 32; r++) h1s[(rb * 32 + r) * 132 + u] = geluf(accv[r] + b1);
    }
    __syncthreads();

    // hidden2: unit u = t%64, rows block rb = t/64 (16 rows each)
    {
        const int u = t & 63, rb = t >> 6;
        float accv[16];
#pragma unroll
        for (int r = 0; r < 16; r++) accv[r] = 0.f;
        const float* hb = h1s + (rb * 16) * 132;
        for (int d0 = 0; d0 < H_; d0 += 4) {
            float w0 = hw2[(d0 + 0) * 64 + u];
            float w1 = hw2[(d0 + 1) * 64 + u];
            float w2 = hw2[(d0 + 2) * 64 + u];
            float w3 = hw2[(d0 + 3) * 64 + u];
#pragma unroll
            for (int r = 0; r < 16; r++) {
                float4 hv = *reinterpret_cast<const float4*>(hb + r * 132 + d0);
                accv[r] += hv.x * w0 + hv.y * w1 + hv.z * w2 + hv.w * w3;
            }
        }
        float b2 = hb2[u];
#pragma unroll
        for (int r = 0; r < 16; r++) h2s[(rb * 16 + r) * 65 + u] = geluf(accv[r] + b2);
    }
    __syncthreads();

    if (t < 64) {
        float s = hb3[0];
#pragma unroll 8
        for (int j = 0; j < 64; j++) s += h2s[t * 65 + j] * hw3[j];
        g_dG[row0 + t] = s;
    }
}

// ============================================================
// masked mean over L, per batch
// ============================================================
__global__ void k_final(const float* __restrict__ mask, float* __restrict__ out) {
    const int w = threadIdx.x >> 5, lane = threadIdx.x & 31;
    if (w < B_) {
        float s = 0.f, ms = 0.f;
        for (int l = lane; l < L_; l += 32) {
            float mk = mask[w * L_ + l];
            s  += g_dG[w * L_ + l] * mk;
            ms += mk;
        }
#pragma unroll
        for (int o = 16; o; o >>= 1) {
            s  += __shfl_down_sync(0xffffffff, s, o);
            ms += __shfl_down_sync(0xffffffff, ms, o);
        }
        if (lane == 0) out[w] = s / sqrtf(fmaxf(ms, 1.0f));
    }
}

// ============================================================
extern "C" void kernel_launch(void* const* d_in, const int* in_sizes, int n_in,
                              void* d_out, int out_size)
{
    const float* h_V  = (const float*)d_in[0];
    const float* h_E  = (const float*)d_in[1];
    const float* mask = (const float*)d_in[2];
    const float* fw1  = (const float*)d_in[3];
    const float* fb1  = (const float*)d_in[4];
    const float* fw2  = (const float*)d_in[5];
    const float* fb2  = (const float*)d_in[6];
    const float* hw1  = (const float*)d_in[7];
    const float* hb1  = (const float*)d_in[8];
    const float* hw2  = (const float*)d_in[9];
    const float* hb2  = (const float*)d_in[10];
    const float* hw3  = (const float*)d_in[11];
    const float* hb3  = (const float*)d_in[12];
    const int*   E_idx = (const int*)d_in[13];
    float* out = (float*)d_out;

    cudaFuncSetAttribute(k_main, cudaFuncAttributeMaxDynamicSharedMemorySize, SMEM_MAIN);
    cudaFuncSetAttribute(k_head, cudaFuncAttributeMaxDynamicSharedMemorySize, SMEM_HEAD);

    k_convert<<<192, 256>>>(fw1, fw2);
    k_main<<<NTILES, 256, SMEM_MAIN>>>(h_V, h_E, fb1, fb2, E_idx);
    k_head<<<B_ * L_ / 64, 256, SMEM_HEAD>>>(hw1, hb1, hw2, hb2, hw3, hb3);
    k_final<<<1, 512>>>(mask, out);
}

// round 2
// speedup vs baseline: 1.0058x; 1.0058x over previous
#include <cuda_runtime.h>
#include <cuda_fp16.h>
#include <mma.h>
#include <cstdint>

using namespace nvcuda;

// Problem dims
#define B_  16
#define L_  512
#define Kn_ 48
#define E_  128
#define D_  384
#define H_  128

#define TILE_M  96
#define NTILES  4096          // (B*L*K)/TILE_M = 393216/96

// ---- smem layout (bytes) for k_main ----
// A1s   [96][392] half : 0       .. 75264
// Xs    [96][136] half : 75264   .. 101376
// W1s   [128][392]half : 101376  .. 201728
// C1s   [96][388] f32  : alias @75264  (after GEMM1; Xs/W1s dead)  end 224256
// CHK0  [64][392] half : alias @76800  (after A1s written; C1s dead)
// CHK1  [64][392] half : alias @126976
// C2s   [96][388] f32  : alias @76800  (after GEMM2; chunks dead)  end 225792
// idxs  [96] int       : 225792 .. 226176
#define OFF_A1S   0
#define OFF_XS    75264
#define OFF_W1S   101376
#define OFF_C1S   75264
#define OFF_CHK0  76800
#define OFF_CHK1  126976
#define OFF_C2S   76800
#define OFF_IDX   225792
#define SMEM_MAIN 226304

// head kernel smem
#define HOFF_HS   0            // [64][388] f32 = 99328
#define HOFF_H1   99328        // [64][132] f32 = 33792
#define HOFF_H2   133120       // [64][65]  f32 = 16640
#define SMEM_HEAD 149760

// ---- device scratch (no allocations allowed) ----
__device__ __align__(16) __half g_W1h[E_ * D_];
__device__ __align__(16) __half g_W2h[D_ * D_];
__device__ __align__(16) float  g_hbuf[(size_t)B_ * L_ * D_];
__device__ __align__(16) float  g_dG[B_ * L_];

__device__ __forceinline__ float geluf(float x) {
    return 0.5f * x * (1.0f + erff(x * 0.7071067811865476f));
}

__device__ __forceinline__ void cp_async16(void* dst, const void* src) {
    unsigned s = (unsigned)__cvta_generic_to_shared(dst);
    asm volatile("cp.async.cg.shared.global [%0], [%1], 16;\n" :: "r"(s), "l"(src) : "memory");
}
__device__ __forceinline__ void cp_commit() { asm volatile("cp.async.commit_group;\n" ::: "memory"); }
__device__ __forceinline__ void cp_wait0()  { asm volatile("cp.async.wait_group 0;\n" ::: "memory"); }

// ============================================================
// weight fp32 -> fp16 conversion (tiny)
// ============================================================
__global__ void k_convert(const float* __restrict__ fw1, const float* __restrict__ fw2) {
    int stride = gridDim.x * blockDim.x;
    int i0 = blockIdx.x * blockDim.x + threadIdx.x;
    for (int q = i0; q < E_ * D_; q += stride) g_W1h[q] = __float2half_rn(fw1[q]);
    for (int q = i0; q < D_ * D_; q += stride) g_W2h[q] = __float2half_rn(fw2[q]);
}

// ============================================================
// fused: GEMM1 + gelu + GEMM2 + gelu + gather(x_j) + K-reduce
// one CTA = 96 rows = 2 complete (b,l) groups -> writes 2 rows of h
// ============================================================
__global__ void __launch_bounds__(256, 1)
k_main(const float* __restrict__ h_V, const float* __restrict__ h_E,
       const float* __restrict__ fb1, const float* __restrict__ fb2,
       const int* __restrict__ E_idx)
{
    extern __shared__ unsigned char smem[];
    __half* A1s  = (__half*)(smem + OFF_A1S);    // [96][392]
    __half* Xs   = (__half*)(smem + OFF_XS);     // [96][136]
    __half* W1s  = (__half*)(smem + OFF_W1S);    // [128][392]
    float*  C1s  = (float*)(smem + OFF_C1S);     // [96][388]
    float*  C2s  = (float*)(smem + OFF_C2S);     // [96][388]
    __half* chk0 = (__half*)(smem + OFF_CHK0);   // [64][392]
    __half* chk1 = (__half*)(smem + OFF_CHK1);   // [64][392]
    int*    idxs = (int*)(smem + OFF_IDX);

    const int t = threadIdx.x;
    const int tile = blockIdx.x;
    const int rowbase = tile * TILE_M;
    const int b = rowbase / (L_ * Kn_);          // whole tile within one batch

    if (t < TILE_M) idxs[t] = E_idx[rowbase + t];

    // ---- stage W1 (fp16, cp.async) and X tile (fp32->fp16) ----
    for (int q = t; q < (E_ * D_) / 8; q += 256) {        // 6144 x 16B
        int r = q / 48, c8 = q - r * 48;
        cp_async16(W1s + r * 392 + c8 * 8, g_W1h + r * 384 + c8 * 8);
    }
    cp_commit();
    {
        const float4* Xg = reinterpret_cast<const float4*>(h_E + (size_t)rowbase * E_);
        for (int q = t; q < (TILE_M * E_) / 4; q += 256) {  // 3072 float4
            int m = q >> 5, c4 = q & 31;
            float4 v = Xg[q];
            __half2* d = reinterpret_cast<__half2*>(Xs + m * 136 + c4 * 4);
            d[0] = __floats2half2_rn(v.x, v.y);
            d[1] = __floats2half2_rn(v.z, v.w);
        }
    }
    cp_wait0();
    __syncthreads();

    // warp tiling: 8 warps in 2(m) x 4(n); warp tile = 48 x 96
    const int warp  = t >> 5;
    const int wm    = warp >> 2;     // 0..1
    const int wn    = warp & 3;      // 0..3
    const int mrow0 = wm * 48;
    const int ncol0 = wn * 96;

    wmma::fragment<wmma::accumulator, 16, 16, 16, float> acc[3][6];
#pragma unroll
    for (int i = 0; i < 3; i++)
#pragma unroll
        for (int j = 0; j < 6; j++) wmma::fill_fragment(acc[i][j], 0.0f);

    // ---- GEMM1: [96,128] @ [128,384] ----
#pragma unroll
    for (int k = 0; k < E_; k += 16) {
        wmma::fragment<wmma::matrix_a, 16, 16, 16, __half, wmma::row_major> af[3];
#pragma unroll
        for (int i = 0; i < 3; i++)
            wmma::load_matrix_sync(af[i], Xs + (mrow0 + i * 16) * 136 + k, 136);
#pragma unroll
        for (int j = 0; j < 6; j++) {
            wmma::fragment<wmma::matrix_b, 16, 16, 16, __half, wmma::row_major> bf;
            wmma::load_matrix_sync(bf, W1s + k * 392 + ncol0 + j * 16, 392);
#pragma unroll
            for (int i = 0; i < 3; i++) wmma::mma_sync(acc[i][j], af[i], bf, acc[i][j]);
        }
    }
    __syncthreads();   // all mma reads of Xs/W1s done before aliasing with C1s
#pragma unroll
    for (int i = 0; i < 3; i++)
#pragma unroll
        for (int j = 0; j < 6; j++)
            wmma::store_matrix_sync(C1s + (mrow0 + i * 16) * 388 + ncol0 + j * 16,
                                    acc[i][j], 388, wmma::mem_row_major);
    __syncthreads();

    // ---- bias + gelu -> A1s (fp16) ----
    for (int e = t; e < TILE_M * D_; e += 256) {
        int m = e / D_, n = e - m * D_;
        float v = C1s[m * 388 + n] + fb1[n];
        A1s[m * 392 + n] = __float2half_rn(geluf(v));
    }
    __syncthreads();   // C1s dead; chunk buffers may overwrite

    // ---- GEMM2: [96,384] @ [384,384], W2 streamed in 6 chunks of k=64 ----
#pragma unroll
    for (int i = 0; i < 3; i++)
#pragma unroll
        for (int j = 0; j < 6; j++) wmma::fill_fragment(acc[i][j], 0.0f);

    auto load_chunk = [&](int c, __half* dst) {
        const __half* src = g_W2h + (size_t)c * 64 * D_;
        for (int q = t; q < 3072; q += 256) {         // 64 rows x 48 x 16B
            int r = q / 48, c8 = q - r * 48;
            cp_async16(dst + r * 392 + c8 * 8, src + r * 384 + c8 * 8);
        }
    };
    load_chunk(0, chk0);
    cp_commit(); cp_wait0();
    __syncthreads();

    for (int c = 0; c < 6; c++) {
        __half* cur = (c & 1) ? chk1 : chk0;
        if (c < 5) { load_chunk(c + 1, (c & 1) ? chk0 : chk1); cp_commit(); }
#pragma unroll
        for (int ks = 0; ks < 4; ks++) {
            int k2 = c * 64 + ks * 16;
            wmma::fragment<wmma::matrix_a, 16, 16, 16, __half, wmma::row_major> af[3];
#pragma unroll
            for (int i = 0; i < 3; i++)
                wmma::load_matrix_sync(af[i], A1s + (mrow0 + i * 16) * 392 + k2, 392);
#pragma unroll
            for (int j = 0; j < 6; j++) {
                wmma::fragment<wmma::matrix_b, 16, 16, 16, __half, wmma::row_major> bf;
                wmma::load_matrix_sync(bf, cur + (ks * 16) * 392 + ncol0 + j * 16, 392);
#pragma unroll
                for (int i = 0; i < 3; i++) wmma::mma_sync(acc[i][j], af[i], bf, acc[i][j]);
            }
        }
        if (c < 5) cp_wait0();
        __syncthreads();
    }

    // ---- store C2, then fused bias+gelu+gather+K-reduce epilogue ----
#pragma unroll
    for (int i = 0; i < 3; i++)
#pragma unroll
        for (int j = 0; j < 6; j++)
            wmma::store_matrix_sync(C2s + (mrow0 + i * 16) * 388 + ncol0 + j * 16,
                                    acc[i][j], 388, wmma::mem_row_major);
    __syncthreads();

    {
        const int n0 = t;                 // < 256
        const int n1 = 256 + t;           // valid when t < 128
        const bool has1 = (t < 128);
        float fa = fb2[n0];
        float fbv = has1 ? fb2[n1] : 0.0f;
        const float* hVb = h_V + (size_t)b * L_ * D_;

        float a00 = 0.f, a01 = 0.f, a10 = 0.f, a11 = 0.f;
#pragma unroll 4
        for (int m = 0; m < 48; m++) {
            const float* xr = hVb + (size_t)idxs[m] * D_;
            float w0 = geluf(C2s[m * 388 + n0] + fa);
            a00 += w0 * xr[n0];
            if (has1) { float w1 = geluf(C2s[m * 388 + n1] + fbv); a01 += w1 * xr[n1]; }
        }
#pragma unroll 4
        for (int m = 48; m < 96; m++) {
            const float* xr = hVb + (size_t)idxs[m] * D_;
            float w0 = geluf(C2s[m * 388 + n0] + fa);
            a10 += w0 * xr[n0];
            if (has1) { float w1 = geluf(C2s[m * 388 + n1] + fbv); a11 += w1 * xr[n1]; }
        }
        const size_t g0 = (size_t)tile * 2;
        g_hbuf[g0 * D_ + n0] = a00;
        g_hbuf[(g0 + 1) * D_ + n0] = a10;
        if (has1) {
            g_hbuf[g0 * D_ + n1] = a01;
            g_hbuf[(g0 + 1) * D_ + n1] = a11;
        }
    }
}

// ============================================================
// head MLP: h[8192,384] -> gelu(@hw1) -> gelu(@hw2) -> @hw3 -> dG[8192]
// one CTA = 64 rows, 256 threads
// ============================================================
__global__ void __launch_bounds__(256, 1)
k_head(const float* __restrict__ hw1, const float* __restrict__ hb1,
       const float* __restrict__ hw2, const float* __restrict__ hb2,
       const float* __restrict__ hw3, const float* __restrict__ hb3)
{
    extern __shared__ unsigned char sm[];
    float* hs  = (float*)(sm + HOFF_HS);   // [64][388]
    float* h1s = (float*)(sm + HOFF_H1);   // [64][132]
    float* h2s = (float*)(sm + HOFF_H2);   // [64][65]
    const int t = threadIdx.x;
    const int row0 = blockIdx.x * 64;

    for (int e = t; e < 64 * D_; e += 256) {
        int r = e / D_, n = e - r * D_;
        hs[r * 388 + n] = g_hbuf[(size_t)(row0 + r) * D_ + n];
    }
    __syncthreads();

    // hidden1: unit u = t%128, rows block rb = t/128 (32 rows each)
    {
        const int u = t & 127, rb = t >> 7;
        float accv[32];
#pragma unroll
        for (int r = 0; r < 32; r++) accv[r] = 0.f;
        const float* hb = hs + (rb * 32) * 388;
        for (int d0 = 0; d0 < D_; d0 += 4) {
            float w0 = hw1[(d0 + 0) * H_ + u];
            float w1 = hw1[(d0 + 1) * H_ + u];
            float w2 = hw1[(d0 + 2) * H_ + u];
            float w3 = hw1[(d0 + 3) * H_ + u];
#pragma unroll
            for (int r = 0; r < 32; r++) {
                float4 hv = *reinterpret_cast<const float4*>(hb + r * 388 + d0);
                accv[r] += hv.x * w0 + hv.y * w1 + hv.z * w2 + hv.w * w3;
            }
        }
        float b1 = hb1[u];
#pragma unroll
        for (int r = 0; r < 32; r++) h1s[(rb * 32 + r) * 132 + u] = geluf(accv[r] + b1);
    }
    __syncthreads();

    // hidden2: unit u = t%64, rows block rb = t/64 (16 rows each)
    {
        const int u = t & 63, rb = t >> 6;
        float accv[16];
#pragma unroll
        for (int r = 0; r < 16; r++) accv[r] = 0.f;
        const float* hb = h1s + (rb * 16) * 132;
        for (int d0 = 0; d0 < H_; d0 += 4) {
            float w0 = hw2[(d0 + 0) * 64 + u];
            float w1 = hw2[(d0 + 1) * 64 + u];
            float w2 = hw2[(d0 + 2) * 64 + u];
            float w3 = hw2[(d0 + 3) * 64 + u];
#pragma unroll
            for (int r = 0; r < 16; r++) {
                float4 hv = *reinterpret_cast<const float4*>(hb + r * 132 + d0);
                accv[r] += hv.x * w0 + hv.y * w1 + hv.z * w2 + hv.w * w3;
            }
        }
        float b2 = hb2[u];
#pragma unroll
        for (int r = 0; r < 16; r++) h2s[(rb * 16 + r) * 65 + u] = geluf(accv[r] + b2);
    }
    __syncthreads();

    if (t < 64) {
        float s = hb3[0];
#pragma unroll 8
        for (int j = 0; j < 64; j++) s += h2s[t * 65 + j] * hw3[j];
        g_dG[row0 + t] = s;
    }
}

// ============================================================
// masked mean over L, per batch
// ============================================================
__global__ void k_final(const float* __restrict__ mask, float* __restrict__ out) {
    const int w = threadIdx.x >> 5, lane = threadIdx.x & 31;
    if (w < B_) {
        float s = 0.f, ms = 0.f;
        for (int l = lane; l < L_; l += 32) {
            float mk = mask[w * L_ + l];
            s  += g_dG[w * L_ + l] * mk;
            ms += mk;
        }
#pragma unroll
        for (int o = 16; o; o >>= 1) {
            s  += __shfl_down_sync(0xffffffff, s, o);
            ms += __shfl_down_sync(0xffffffff, ms, o);
        }
        if (lane == 0) out[w] = s / sqrtf(fmaxf(ms, 1.0f));
    }
}

// ============================================================
extern "C" void kernel_launch(void* const* d_in, const int* in_sizes, int n_in,
                              void* d_out, int out_size)
{
    const float* h_V  = (const float*)d_in[0];
    const float* h_E  = (const float*)d_in[1];
    const float* mask = (const float*)d_in[2];
    const float* fw1  = (const float*)d_in[3];
    const float* fb1  = (const float*)d_in[4];
    const float* fw2  = (const float*)d_in[5];
    const float* fb2  = (const float*)d_in[6];
    const float* hw1  = (const float*)d_in[7];
    const float* hb1  = (const float*)d_in[8];
    const float* hw2  = (const float*)d_in[9];
    const float* hb2  = (const float*)d_in[10];
    const float* hw3  = (const float*)d_in[11];
    const float* hb3  = (const float*)d_in[12];
    const int*   E_idx = (const int*)d_in[13];
    float* out = (float*)d_out;

    cudaFuncSetAttribute(k_main, cudaFuncAttributeMaxDynamicSharedMemorySize, SMEM_MAIN);
    cudaFuncSetAttribute(k_head, cudaFuncAttributeMaxDynamicSharedMemorySize, SMEM_HEAD);

    k_convert<<<192, 256>>>(fw1, fw2);
    k_main<<<NTILES, 256, SMEM_MAIN>>>(h_V, h_E, fb1, fb2, E_idx);
    k_head<<<B_ * L_ / 64, 256, SMEM_HEAD>>>(hw1, hb1, hw2, hb2, hw3, hb3);
    k_final<<<1, 512>>>(mask, out);
}